// round 15
// baseline (speedup 1.0000x reference)
#include <cuda_runtime.h>
#include <cuda_fp16.h>
#include <mma.h>
#include <math.h>

using namespace nvcuda;

#define N_NODES   40000
#define N_EDGES   640000
#define FDIM      128
#define N_GRAPHS  64
#define N_CLASSES 10
#define MAXDEG    64        // Poisson(16) in-degree; P(>=64) ~ 1e-20

// ---------------- scratch (device globals; no allocations) ------------------
__device__ __align__(16) __half g_A16[N_NODES * FDIM];
__device__ __align__(16) __half g_B16[N_NODES * FDIM];
__device__ __align__(16) __half g_Whi[2 * FDIM * FDIM];   // W2,W3 hi
__device__ __align__(16) __half g_Wlo[2 * FDIM * FDIM];   // W2,W3 lo
__device__ int    g_indeg[N_NODES];
__device__ float  g_dis[N_NODES];
__device__ int2   g_ew[N_NODES * MAXDEG];    // padded CSR: (src, dis[src] bits)
__device__ float  g_sums[N_GRAPHS * FDIM];
__device__ float  g_cnts[N_GRAPHS];

// ---------------- init: zero indeg + pool sums ------------------------------
__global__ void init_kernel() {
    int i = blockIdx.x * blockDim.x + threadIdx.x;
    if (i < N_NODES) g_indeg[i] = 0;
    if (i < N_GRAPHS * FDIM) g_sums[i] = 0.f;
    if (i < N_GRAPHS) g_cnts[i] = 0.f;
}

// ---------------- W2/W3 Markidis split -> fp16 globals (side stream) ---------
__global__ void w_split_kernel(const float* __restrict__ W2,
                               const float* __restrict__ W3) {
    int idx = blockIdx.x * blockDim.x + threadIdx.x;
    if (idx >= FDIM * FDIM) return;
    const float* Ws[2] = {W2, W3};
#pragma unroll
    for (int l = 0; l < 2; l++) {
        float w = Ws[l][idx];
        __half hi = __float2half_rn(w);
        float lo = w - __half2float(hi);
        g_Whi[l * FDIM * FDIM + idx] = hi;
        g_Wlo[l * FDIM * FDIM + idx] = __float2half_rn(lo);
    }
}

// ---------------- single-pass padded-CSR fill (src only) ---------------------
__global__ void fill_direct_kernel(const int* __restrict__ row,
                                   const int* __restrict__ col) {
    int e = blockIdx.x * blockDim.x + threadIdx.x;
    if (e >= N_EDGES) return;
    int r = row[e];
    int c = col[e];
    int p = atomicAdd(&g_indeg[c], 1);
    if (p < MAXDEG) g_ew[c * MAXDEG + p].x = r;
}

// ---------------- dis = rsqrt(deg+1) -----------------------------------------
__global__ void dis_kernel() {
    int i = blockIdx.x * blockDim.x + threadIdx.x;
    if (i < N_NODES) g_dis[i] = rsqrtf((float)(g_indeg[i] + 1));
}

// ---------------- post-pass: embed weight = dis[src] into payload ------------
__global__ void wt_kernel() {
    int i = blockIdx.x * blockDim.x + threadIdx.x;    // over N_NODES*MAXDEG
    if (i >= N_NODES * MAXDEG) return;
    int node = i >> 6;                                 // /MAXDEG
    int slot = i & (MAXDEG - 1);
    int deg = g_indeg[node]; if (deg > MAXDEG) deg = MAXDEG;
    if (slot < deg) {
        int s = g_ew[i].x;
        g_ew[i].y = __float_as_int(g_dis[s]);
    }
}

// ---------------- shared helpers ---------------------------------------------
__device__ __forceinline__ float4 h4_to_f4(uint2 u) {
    __half2 a = *(__half2*)&u.x;
    __half2 b = *(__half2*)&u.y;
    float2 fa = __half22float2(a);
    float2 fb = __half22float2(b);
    return make_float4(fa.x, fa.y, fb.x, fb.y);
}

// ---------------- GEMM pieces (BM=64, R13-proven) -----------------------------
#define GEMM_BM  64
#define LDP      136
#define GEMM_SMEM_BYTES ((2 * 128 * LDP + GEMM_BM * LDP) * 2)

// inline split of fp32 W (layer 1 only; overlapped with side stream)
__device__ __forceinline__ void stage_w_split_f32(const float* __restrict__ W,
                                                  __half* Wh, __half* Wl, int tid) {
    const float4* W4 = (const float4*)W;
#pragma unroll
    for (int i = 0; i < 16; i++) {
        int idx = tid + 256 * i;
        float4 w = W4[idx];
        int r = idx >> 5, c = (idx & 31) * 4;
        __half h0 = __float2half_rn(w.x);
        __half h1 = __float2half_rn(w.y);
        __half h2 = __float2half_rn(w.z);
        __half h3 = __float2half_rn(w.w);
        __half l0 = __float2half_rn(w.x - __half2float(h0));
        __half l1 = __float2half_rn(w.y - __half2float(h1));
        __half l2 = __float2half_rn(w.z - __half2float(h2));
        __half l3 = __float2half_rn(w.w - __half2float(h3));
        __half2 hh0 = __halves2half2(h0, h1);
        __half2 hh1 = __halves2half2(h2, h3);
        __half2 ll0 = __halves2half2(l0, l1);
        __half2 ll1 = __halves2half2(l2, l3);
        uint2 uh; uh.x = *(unsigned*)&hh0; uh.y = *(unsigned*)&hh1;
        uint2 ul; ul.x = *(unsigned*)&ll0; ul.y = *(unsigned*)&ll1;
        *(uint2*)(Wh + r * LDP + c) = uh;
        *(uint2*)(Wl + r * LDP + c) = ul;
    }
}

// prestaged fp16 W copy (layers 2,3): pure float4 copies
__device__ __forceinline__ void stage_w_f16(const __half* __restrict__ Whi,
                                            const __half* __restrict__ Wlo,
                                            __half* Wh, __half* Wl, int tid) {
    const float4* H4 = (const float4*)Whi;
    const float4* L4 = (const float4*)Wlo;
#pragma unroll
    for (int i = 0; i < 8; i++) {
        int idx = tid + 256 * i;          // float4 = 8 halves; 16 per row
        int r = idx >> 4, c8 = idx & 15;
        *(float4*)(Wh + r * LDP + c8 * 8) = H4[idx];
        *(float4*)(Wl + r * LDP + c8 * 8) = L4[idx];
    }
}

__device__ __forceinline__ void wmma_tile(const __half* Wh, const __half* Wl,
                                          const __half* Xs, __half* __restrict__ Y,
                                          int row0, int tid) {
    int warp = tid >> 5;
    int wr = warp >> 1;
    int wc = warp & 1;

    wmma::fragment<wmma::matrix_a, 16, 16, 16, __half, wmma::row_major> a_frag;
    wmma::fragment<wmma::matrix_b, 16, 16, 16, __half, wmma::row_major> bh, bl;
    wmma::fragment<wmma::accumulator, 16, 16, 16, float> acc[4];
#pragma unroll
    for (int j = 0; j < 4; j++) wmma::fill_fragment(acc[j], 0.0f);

#pragma unroll
    for (int kk = 0; kk < 8; kk++) {
        wmma::load_matrix_sync(a_frag, Xs + (wr * 16) * LDP + kk * 16, LDP);
#pragma unroll
        for (int j = 0; j < 4; j++) {
            int coff = wc * 64 + j * 16;
            wmma::load_matrix_sync(bh, Wh + (kk * 16) * LDP + coff, LDP);
            wmma::mma_sync(acc[j], a_frag, bh, acc[j]);
            wmma::load_matrix_sync(bl, Wl + (kk * 16) * LDP + coff, LDP);
            wmma::mma_sync(acc[j], a_frag, bl, acc[j]);
        }
    }

#pragma unroll
    for (int j = 0; j < 4; j++) {
        wmma::fragment<wmma::accumulator, 16, 16, 16, __half> hfrag;
#pragma unroll
        for (int t = 0; t < hfrag.num_elements; t++)
            hfrag.x[t] = __float2half_rn(acc[j].x[t]);
        wmma::store_matrix_sync(
            Y + (size_t)(row0 + wr * 16) * FDIM + wc * 64 + j * 16,
            hfrag, FDIM, wmma::mem_row_major);
    }
}

// layer 1: fp32 X + inline fp32-W split
__global__ __launch_bounds__(256, 2)
void gemm1_kernel(const float* __restrict__ X,
                  const float* __restrict__ W,
                  __half* __restrict__ Y) {
    extern __shared__ __half smh[];
    __half* Wh = smh;
    __half* Wl = smh + 128 * LDP;
    __half* Xs = smh + 2 * 128 * LDP;

    int tid  = threadIdx.x;
    int row0 = blockIdx.x * GEMM_BM;

    stage_w_split_f32(W, Wh, Wl, tid);

    const float4* X4 = (const float4*)(X + (size_t)row0 * FDIM);
#pragma unroll
    for (int i = 0; i < 8; i++) {
        int idx = tid + 256 * i;
        float4 v = X4[idx];
        int r = idx >> 5, c = (idx & 31) * 4;
        __half2 h0 = __floats2half2_rn(v.x, v.y);
        __half2 h1 = __floats2half2_rn(v.z, v.w);
        uint2 u; u.x = *(unsigned*)&h0; u.y = *(unsigned*)&h1;
        *(uint2*)(Xs + r * LDP + c) = u;
    }
    __syncthreads();

    wmma_tile(Wh, Wl, Xs, Y, row0, tid);
}

// layers 2,3: fp16 X + prestaged fp16 W
__global__ __launch_bounds__(256, 2)
void gemm23_kernel(const __half* __restrict__ X,
                   const __half* __restrict__ Whi,
                   const __half* __restrict__ Wlo,
                   __half* __restrict__ Y) {
    extern __shared__ __half smh[];
    __half* Wh = smh;
    __half* Wl = smh + 128 * LDP;
    __half* Xs = smh + 2 * 128 * LDP;

    int tid  = threadIdx.x;
    int row0 = blockIdx.x * GEMM_BM;

    stage_w_f16(Whi, Wlo, Wh, Wl, tid);

    const float4* X4 = (const float4*)(X + (size_t)row0 * FDIM);
#pragma unroll
    for (int i = 0; i < 4; i++) {
        int idx = tid + 256 * i;
        int r = idx >> 4, c8 = idx & 15;
        *(float4*)(Xs + r * LDP + c8 * 8) = X4[idx];
    }
    __syncthreads();

    wmma_tile(Wh, Wl, Xs, Y, row0, tid);
}

// ---------------- CSR gather (R7 int2-payload loop; dn folded at end) --------
template <int POOL>
__global__ void gather_kernel(const float* __restrict__ bias,
                              const int* __restrict__ batch) {
    int node = blockIdx.x * (blockDim.x >> 5) + (threadIdx.x >> 5);
    if (node >= N_NODES) return;
    int lane = threadIdx.x & 31;

    const uint2* B2 = (const uint2*)g_B16;

    int beg = node * MAXDEG;
    int deg = g_indeg[node];
    if (deg > MAXDEG) deg = MAXDEG;

    float dn = g_dis[node];
    float4 sv = h4_to_f4(B2[(size_t)node * 32 + lane]);
    float4 acc = make_float4(sv.x * dn, sv.y * dn, sv.z * dn, sv.w * dn);

    for (int base = 0; base < deg; base += 32) {
        int rem = deg - base; if (rem > 32) rem = 32;
        int2 my = make_int2(0, 0);
        if (lane < rem) my = __ldg(&g_ew[beg + base + lane]);

        int j = 0;
        for (; j + 4 <= rem; j += 4) {
            int   s0 = __shfl_sync(0xffffffffu, my.x, j);
            int   s1 = __shfl_sync(0xffffffffu, my.x, j + 1);
            int   s2 = __shfl_sync(0xffffffffu, my.x, j + 2);
            int   s3 = __shfl_sync(0xffffffffu, my.x, j + 3);
            float w0 = __int_as_float(__shfl_sync(0xffffffffu, my.y, j));
            float w1 = __int_as_float(__shfl_sync(0xffffffffu, my.y, j + 1));
            float w2 = __int_as_float(__shfl_sync(0xffffffffu, my.y, j + 2));
            float w3 = __int_as_float(__shfl_sync(0xffffffffu, my.y, j + 3));
            float4 v0 = h4_to_f4(__ldg(&B2[(size_t)s0 * 32 + lane]));
            float4 v1 = h4_to_f4(__ldg(&B2[(size_t)s1 * 32 + lane]));
            float4 v2 = h4_to_f4(__ldg(&B2[(size_t)s2 * 32 + lane]));
            float4 v3 = h4_to_f4(__ldg(&B2[(size_t)s3 * 32 + lane]));
            acc.x = fmaf(w0, v0.x, acc.x); acc.y = fmaf(w0, v0.y, acc.y);
            acc.z = fmaf(w0, v0.z, acc.z); acc.w = fmaf(w0, v0.w, acc.w);
            acc.x = fmaf(w1, v1.x, acc.x); acc.y = fmaf(w1, v1.y, acc.y);
            acc.z = fmaf(w1, v1.z, acc.z); acc.w = fmaf(w1, v1.w, acc.w);
            acc.x = fmaf(w2, v2.x, acc.x); acc.y = fmaf(w2, v2.y, acc.y);
            acc.z = fmaf(w2, v2.z, acc.z); acc.w = fmaf(w2, v2.w, acc.w);
            acc.x = fmaf(w3, v3.x, acc.x); acc.y = fmaf(w3, v3.y, acc.y);
            acc.z = fmaf(w3, v3.z, acc.z); acc.w = fmaf(w3, v3.w, acc.w);
        }
        for (; j < rem; j++) {
            int   s = __shfl_sync(0xffffffffu, my.x, j);
            float w = __int_as_float(__shfl_sync(0xffffffffu, my.y, j));
            float4 v = h4_to_f4(__ldg(&B2[(size_t)s * 32 + lane]));
            acc.x = fmaf(w, v.x, acc.x); acc.y = fmaf(w, v.y, acc.y);
            acc.z = fmaf(w, v.z, acc.z); acc.w = fmaf(w, v.w, acc.w);
        }
    }

    float4 bv = __ldg(&((const float4*)bias)[lane]);
    acc.x = fmaxf(fmaf(dn, acc.x, bv.x), 0.f);
    acc.y = fmaxf(fmaf(dn, acc.y, bv.y), 0.f);
    acc.z = fmaxf(fmaf(dn, acc.z, bv.z), 0.f);
    acc.w = fmaxf(fmaf(dn, acc.w, bv.w), 0.f);

    if (POOL) {
        int g = __ldg(&batch[node]);
        float* dst = g_sums + (size_t)g * FDIM + lane * 4;
        asm volatile("red.global.add.v4.f32 [%0], {%1, %2, %3, %4};"
                     :: "l"(dst), "f"(acc.x), "f"(acc.y), "f"(acc.z), "f"(acc.w)
                     : "memory");
        if (lane == 0) atomicAdd(&g_cnts[g], 1.0f);
    } else {
        __half2 h0 = __floats2half2_rn(acc.x, acc.y);
        __half2 h1 = __floats2half2_rn(acc.z, acc.w);
        uint2 u; u.x = *(unsigned*)&h0; u.y = *(unsigned*)&h1;
        ((uint2*)g_A16)[(size_t)node * 32 + lane] = u;
    }
}

// ---------------- final linear ----------------------------------------------
__global__ void final_kernel(const float* __restrict__ Wl,
                             const float* __restrict__ bl,
                             float* __restrict__ out) {
    int g = blockIdx.x;
    int c = threadIdx.x;
    if (c >= N_CLASSES) return;
    float cnt = g_cnts[g];
    float inv = 1.0f / fmaxf(cnt, 1.0f);
    float acc = bl[c];
    for (int k = 0; k < FDIM; k++)
        acc += (g_sums[g * FDIM + k] * inv) * Wl[k * N_CLASSES + c];
    out[g * N_CLASSES + c] = acc;
}

// ---------------- launch ----------------------------------------------------
extern "C" void kernel_launch(void* const* d_in, const int* in_sizes, int n_in,
                              void* d_out, int out_size) {
    const float* x   = (const float*)d_in[0];
    const int*   ei  = (const int*)d_in[1];
    const int*   bat = (const int*)d_in[2];
    const float* W1  = (const float*)d_in[3];
    const float* b1  = (const float*)d_in[4];
    const float* W2  = (const float*)d_in[5];
    const float* b2  = (const float*)d_in[6];
    const float* W3  = (const float*)d_in[7];
    const float* b3  = (const float*)d_in[8];
    const float* Wl  = (const float*)d_in[9];
    const float* bl  = (const float*)d_in[10];
    float* out = (float*)d_out;

    const int* row = ei;
    const int* col = ei + N_EDGES;

    static cudaStream_t s1 = nullptr;
    static cudaEvent_t  ev_fork = nullptr, ev_join = nullptr;
    if (!s1) {
        cudaFuncSetAttribute(gemm1_kernel,
                             cudaFuncAttributeMaxDynamicSharedMemorySize,
                             GEMM_SMEM_BYTES);
        cudaFuncSetAttribute(gemm23_kernel,
                             cudaFuncAttributeMaxDynamicSharedMemorySize,
                             GEMM_SMEM_BYTES);
        cudaStreamCreateWithFlags(&s1, cudaStreamNonBlocking);
        cudaEventCreateWithFlags(&ev_fork, cudaEventDisableTiming);
        cudaEventCreateWithFlags(&ev_join, cudaEventDisableTiming);
    }

    const int gemm_blocks = N_NODES / GEMM_BM;          // 625
    const int node_warp_blocks = (N_NODES + 7) / 8;

    __half* A16; cudaGetSymbolAddress((void**)&A16, g_A16);
    __half* B16; cudaGetSymbolAddress((void**)&B16, g_B16);
    __half* Whi; cudaGetSymbolAddress((void**)&Whi, g_Whi);
    __half* Wlo; cudaGetSymbolAddress((void**)&Wlo, g_Wlo);

    // fork: CSR build + W2/W3 splits on side stream (all hidden under gemm1)
    cudaEventRecord(ev_fork, 0);
    cudaStreamWaitEvent(s1, ev_fork, 0);

    init_kernel<<<(N_NODES + 255) / 256, 256, 0, s1>>>();
    w_split_kernel<<<(FDIM * FDIM + 255) / 256, 256, 0, s1>>>(W2, W3);
    fill_direct_kernel<<<(N_EDGES + 255) / 256, 256, 0, s1>>>(row, col);
    dis_kernel<<<(N_NODES + 255) / 256, 256, 0, s1>>>();
    wt_kernel<<<(N_NODES * MAXDEG + 255) / 256, 256, 0, s1>>>();
    cudaEventRecord(ev_join, s1);

    // main stream: layer-1 GEMM reads fp32 x + fp32 W1 directly
    gemm1_kernel<<<gemm_blocks, 256, GEMM_SMEM_BYTES>>>(x, W1, B16);
    cudaStreamWaitEvent(0, ev_join, 0);

    gather_kernel<0><<<node_warp_blocks, 256>>>(b1, bat);
    gemm23_kernel<<<gemm_blocks, 256, GEMM_SMEM_BYTES>>>(A16, Whi, Wlo, B16);
    gather_kernel<0><<<node_warp_blocks, 256>>>(b2, bat);
    gemm23_kernel<<<gemm_blocks, 256, GEMM_SMEM_BYTES>>>(
        A16, Whi + FDIM * FDIM, Wlo + FDIM * FDIM, B16);
    gather_kernel<1><<<node_warp_blocks, 256>>>(b3, bat);

    final_kernel<<<N_GRAPHS, 32>>>(Wl, bl, out);
}

// round 16
// speedup vs baseline: 1.0245x; 1.0245x over previous
#include <cuda_runtime.h>
#include <cuda_fp16.h>
#include <mma.h>
#include <math.h>

using namespace nvcuda;

#define N_NODES   40000
#define N_EDGES   640000
#define FDIM      128
#define N_GRAPHS  64
#define N_CLASSES 10
#define MAXDEG    64        // Poisson(16) in-degree; P(>=64) ~ 1e-20

#define SPLIT     20032     // 313 * 64 ; h0=[0,SPLIT) h1=[SPLIT,N_NODES)

// ---------------- scratch (device globals; no allocations) ------------------
__device__ __align__(16) __half g_A16[N_NODES * FDIM];
__device__ __align__(16) __half g_B16[N_NODES * FDIM];
__device__ __align__(16) __half g_C16[N_NODES * FDIM];
__device__ int    g_indeg[N_NODES];
__device__ float  g_dis[N_NODES];
__device__ int    g_src[N_NODES * MAXDEG];   // padded CSR: srcs of in-edges
__device__ float  g_sums[N_GRAPHS * FDIM];
__device__ float  g_cnts[N_GRAPHS];

// ---------------- init: zero indeg + pool sums ------------------------------
__global__ void init_kernel() {
    int i = blockIdx.x * blockDim.x + threadIdx.x;
    if (i < N_NODES) g_indeg[i] = 0;
    if (i < N_GRAPHS * FDIM) g_sums[i] = 0.f;
    if (i < N_GRAPHS) g_cnts[i] = 0.f;
}

// ---------------- single-pass padded-CSR fill --------------------------------
__global__ void fill_direct_kernel(const int* __restrict__ row,
                                   const int* __restrict__ col) {
    int e = blockIdx.x * blockDim.x + threadIdx.x;
    if (e >= N_EDGES) return;
    int r = row[e];
    int c = col[e];
    int p = atomicAdd(&g_indeg[c], 1);
    if (p < MAXDEG) g_src[c * MAXDEG + p] = r;
}

// ---------------- dis = rsqrt(deg+1) -----------------------------------------
__global__ void dis_kernel() {
    int i = blockIdx.x * blockDim.x + threadIdx.x;
    if (i < N_NODES) g_dis[i] = rsqrtf((float)(g_indeg[i] + 1));
}

// ---------------- shared helpers ---------------------------------------------
__device__ __forceinline__ float4 h4_to_f4(uint2 u) {
    __half2 a = *(__half2*)&u.x;
    __half2 b = *(__half2*)&u.y;
    float2 fa = __half22float2(a);
    float2 fb = __half22float2(b);
    return make_float4(fa.x, fa.y, fb.x, fb.y);
}

// ---------------- GEMM (BM=64, R13-proven; row_base for half launches) --------
#define GEMM_BM  64
#define LDP      136
#define GEMM_SMEM_BYTES ((2 * 128 * LDP + GEMM_BM * LDP) * 2)

__device__ __forceinline__ void stage_w_split(const float* __restrict__ W,
                                              __half* Wh, __half* Wl, int tid) {
    const float4* W4 = (const float4*)W;
#pragma unroll
    for (int i = 0; i < 16; i++) {
        int idx = tid + 256 * i;
        float4 w = W4[idx];
        int r = idx >> 5, c = (idx & 31) * 4;
        __half h0 = __float2half_rn(w.x);
        __half h1 = __float2half_rn(w.y);
        __half h2 = __float2half_rn(w.z);
        __half h3 = __float2half_rn(w.w);
        __half l0 = __float2half_rn(w.x - __half2float(h0));
        __half l1 = __float2half_rn(w.y - __half2float(h1));
        __half l2 = __float2half_rn(w.z - __half2float(h2));
        __half l3 = __float2half_rn(w.w - __half2float(h3));
        __half2 hh0 = __halves2half2(h0, h1);
        __half2 hh1 = __halves2half2(h2, h3);
        __half2 ll0 = __halves2half2(l0, l1);
        __half2 ll1 = __halves2half2(l2, l3);
        uint2 uh; uh.x = *(unsigned*)&hh0; uh.y = *(unsigned*)&hh1;
        uint2 ul; ul.x = *(unsigned*)&ll0; ul.y = *(unsigned*)&ll1;
        *(uint2*)(Wh + r * LDP + c) = uh;
        *(uint2*)(Wl + r * LDP + c) = ul;
    }
}

template <bool XF32>
__global__ __launch_bounds__(256, 2)
void gemm_wmma_kernel(const void* __restrict__ Xv,
                      const float* __restrict__ W,
                      __half* __restrict__ Y,
                      int row_base) {
    extern __shared__ __half smh[];
    __half* Wh = smh;
    __half* Wl = smh + 128 * LDP;
    __half* Xs = smh + 2 * 128 * LDP;

    int tid  = threadIdx.x;
    int row0 = row_base + blockIdx.x * GEMM_BM;

    stage_w_split(W, Wh, Wl, tid);

    if (XF32) {
        const float4* X4 = (const float4*)((const float*)Xv + (size_t)row0 * FDIM);
#pragma unroll
        for (int i = 0; i < 8; i++) {
            int idx = tid + 256 * i;
            float4 v = X4[idx];
            int r = idx >> 5, c = (idx & 31) * 4;
            __half2 h0 = __floats2half2_rn(v.x, v.y);
            __half2 h1 = __floats2half2_rn(v.z, v.w);
            uint2 u; u.x = *(unsigned*)&h0; u.y = *(unsigned*)&h1;
            *(uint2*)(Xs + r * LDP + c) = u;
        }
    } else {
        const float4* X4 = (const float4*)((const __half*)Xv + (size_t)row0 * FDIM);
#pragma unroll
        for (int i = 0; i < 4; i++) {
            int idx = tid + 256 * i;
            int r = idx >> 4, c8 = idx & 15;
            *(float4*)(Xs + r * LDP + c8 * 8) = X4[idx];
        }
    }
    __syncthreads();

    int warp = tid >> 5;
    int wr = warp >> 1;
    int wc = warp & 1;

    wmma::fragment<wmma::matrix_a, 16, 16, 16, __half, wmma::row_major> a_frag;
    wmma::fragment<wmma::matrix_b, 16, 16, 16, __half, wmma::row_major> bh, bl;
    wmma::fragment<wmma::accumulator, 16, 16, 16, float> acc[4];
#pragma unroll
    for (int j = 0; j < 4; j++) wmma::fill_fragment(acc[j], 0.0f);

#pragma unroll
    for (int kk = 0; kk < 8; kk++) {
        wmma::load_matrix_sync(a_frag, Xs + (wr * 16) * LDP + kk * 16, LDP);
#pragma unroll
        for (int j = 0; j < 4; j++) {
            int coff = wc * 64 + j * 16;
            wmma::load_matrix_sync(bh, Wh + (kk * 16) * LDP + coff, LDP);
            wmma::mma_sync(acc[j], a_frag, bh, acc[j]);
            wmma::load_matrix_sync(bl, Wl + (kk * 16) * LDP + coff, LDP);
            wmma::mma_sync(acc[j], a_frag, bl, acc[j]);
        }
    }

#pragma unroll
    for (int j = 0; j < 4; j++) {
        wmma::fragment<wmma::accumulator, 16, 16, 16, __half> hfrag;
#pragma unroll
        for (int t = 0; t < hfrag.num_elements; t++)
            hfrag.x[t] = __float2half_rn(acc[j].x[t]);
        wmma::store_matrix_sync(
            Y + (size_t)(row0 + wr * 16) * FDIM + wc * 64 + j * 16,
            hfrag, FDIM, wmma::mem_row_major);
    }
}

// ---------------- CSR gather (R13-proven; node range + in/out params) --------
template <int POOL>
__global__ void gather_kernel(const __half* __restrict__ Bin,
                              __half* __restrict__ Aout,
                              const float* __restrict__ bias,
                              const int* __restrict__ batch,
                              int node_lo, int node_hi) {
    int node = node_lo + blockIdx.x * (blockDim.x >> 5) + (threadIdx.x >> 5);
    if (node >= node_hi) return;
    int lane = threadIdx.x & 31;

    const uint2* B2 = (const uint2*)Bin;

    int beg = node * MAXDEG;
    int deg = g_indeg[node];
    if (deg > MAXDEG) deg = MAXDEG;

    float dn = g_dis[node];
    float4 sv = h4_to_f4(B2[(size_t)node * 32 + lane]);
    float4 acc = make_float4(sv.x * dn, sv.y * dn, sv.z * dn, sv.w * dn);

    for (int base = 0; base < deg; base += 32) {
        int rem = deg - base; if (rem > 32) rem = 32;
        int   mysrc = 0;
        float myw   = 0.f;
        if (lane < rem) {
            mysrc = __ldg(&g_src[beg + base + lane]);
            myw   = __ldg(&g_dis[mysrc]);
        }

        int j = 0;
        for (; j + 4 <= rem; j += 4) {
            int   s0 = __shfl_sync(0xffffffffu, mysrc, j);
            int   s1 = __shfl_sync(0xffffffffu, mysrc, j + 1);
            int   s2 = __shfl_sync(0xffffffffu, mysrc, j + 2);
            int   s3 = __shfl_sync(0xffffffffu, mysrc, j + 3);
            float w0 = __shfl_sync(0xffffffffu, myw, j);
            float w1 = __shfl_sync(0xffffffffu, myw, j + 1);
            float w2 = __shfl_sync(0xffffffffu, myw, j + 2);
            float w3 = __shfl_sync(0xffffffffu, myw, j + 3);
            float4 v0 = h4_to_f4(__ldg(&B2[(size_t)s0 * 32 + lane]));
            float4 v1 = h4_to_f4(__ldg(&B2[(size_t)s1 * 32 + lane]));
            float4 v2 = h4_to_f4(__ldg(&B2[(size_t)s2 * 32 + lane]));
            float4 v3 = h4_to_f4(__ldg(&B2[(size_t)s3 * 32 + lane]));
            acc.x = fmaf(w0, v0.x, acc.x); acc.y = fmaf(w0, v0.y, acc.y);
            acc.z = fmaf(w0, v0.z, acc.z); acc.w = fmaf(w0, v0.w, acc.w);
            acc.x = fmaf(w1, v1.x, acc.x); acc.y = fmaf(w1, v1.y, acc.y);
            acc.z = fmaf(w1, v1.z, acc.z); acc.w = fmaf(w1, v1.w, acc.w);
            acc.x = fmaf(w2, v2.x, acc.x); acc.y = fmaf(w2, v2.y, acc.y);
            acc.z = fmaf(w2, v2.z, acc.z); acc.w = fmaf(w2, v2.w, acc.w);
            acc.x = fmaf(w3, v3.x, acc.x); acc.y = fmaf(w3, v3.y, acc.y);
            acc.z = fmaf(w3, v3.z, acc.z); acc.w = fmaf(w3, v3.w, acc.w);
        }
        for (; j < rem; j++) {
            int   s = __shfl_sync(0xffffffffu, mysrc, j);
            float w = __shfl_sync(0xffffffffu, myw, j);
            float4 v = h4_to_f4(__ldg(&B2[(size_t)s * 32 + lane]));
            acc.x = fmaf(w, v.x, acc.x); acc.y = fmaf(w, v.y, acc.y);
            acc.z = fmaf(w, v.z, acc.z); acc.w = fmaf(w, v.w, acc.w);
        }
    }

    float4 bv = __ldg(&((const float4*)bias)[lane]);
    acc.x = fmaxf(fmaf(dn, acc.x, bv.x), 0.f);
    acc.y = fmaxf(fmaf(dn, acc.y, bv.y), 0.f);
    acc.z = fmaxf(fmaf(dn, acc.z, bv.z), 0.f);
    acc.w = fmaxf(fmaf(dn, acc.w, bv.w), 0.f);

    if (POOL) {
        int g = __ldg(&batch[node]);
        float* dst = g_sums + (size_t)g * FDIM + lane * 4;
        asm volatile("red.global.add.v4.f32 [%0], {%1, %2, %3, %4};"
                     :: "l"(dst), "f"(acc.x), "f"(acc.y), "f"(acc.z), "f"(acc.w)
                     : "memory");
        if (lane == 0) atomicAdd(&g_cnts[g], 1.0f);
    } else {
        __half2 h0 = __floats2half2_rn(acc.x, acc.y);
        __half2 h1 = __floats2half2_rn(acc.z, acc.w);
        uint2 u; u.x = *(unsigned*)&h0; u.y = *(unsigned*)&h1;
        ((uint2*)Aout)[(size_t)node * 32 + lane] = u;
    }
}

// ---------------- final linear ----------------------------------------------
__global__ void final_kernel(const float* __restrict__ Wl,
                             const float* __restrict__ bl,
                             float* __restrict__ out) {
    int g = blockIdx.x;
    int c = threadIdx.x;
    if (c >= N_CLASSES) return;
    float cnt = g_cnts[g];
    float inv = 1.0f / fmaxf(cnt, 1.0f);
    float acc = bl[c];
    for (int k = 0; k < FDIM; k++)
        acc += (g_sums[g * FDIM + k] * inv) * Wl[k * N_CLASSES + c];
    out[g * N_CLASSES + c] = acc;
}

// ---------------- launch ----------------------------------------------------
extern "C" void kernel_launch(void* const* d_in, const int* in_sizes, int n_in,
                              void* d_out, int out_size) {
    const float* x   = (const float*)d_in[0];
    const int*   ei  = (const int*)d_in[1];
    const int*   bat = (const int*)d_in[2];
    const float* W1  = (const float*)d_in[3];
    const float* b1  = (const float*)d_in[4];
    const float* W2  = (const float*)d_in[5];
    const float* b2  = (const float*)d_in[6];
    const float* W3  = (const float*)d_in[7];
    const float* b3  = (const float*)d_in[8];
    const float* Wl  = (const float*)d_in[9];
    const float* bl  = (const float*)d_in[10];
    float* out = (float*)d_out;

    const int* row = ei;
    const int* col = ei + N_EDGES;

    static cudaStream_t s1 = nullptr;
    static cudaEvent_t ev_fork = nullptr, ev_join = nullptr;
    static cudaEvent_t evA = nullptr, evB = nullptr, evC = nullptr, evE = nullptr;
    if (!s1) {
        cudaFuncSetAttribute(gemm_wmma_kernel<true>,
                             cudaFuncAttributeMaxDynamicSharedMemorySize,
                             GEMM_SMEM_BYTES);
        cudaFuncSetAttribute(gemm_wmma_kernel<false>,
                             cudaFuncAttributeMaxDynamicSharedMemorySize,
                             GEMM_SMEM_BYTES);
        cudaStreamCreateWithFlags(&s1, cudaStreamNonBlocking);
        cudaEventCreateWithFlags(&ev_fork, cudaEventDisableTiming);
        cudaEventCreateWithFlags(&ev_join, cudaEventDisableTiming);
        cudaEventCreateWithFlags(&evA, cudaEventDisableTiming);
        cudaEventCreateWithFlags(&evB, cudaEventDisableTiming);
        cudaEventCreateWithFlags(&evC, cudaEventDisableTiming);
        cudaEventCreateWithFlags(&evE, cudaEventDisableTiming);
    }

    const int gemm_blocks_all = N_NODES / GEMM_BM;          // 625
    const int gemm_blocks_h0  = SPLIT / GEMM_BM;            // 313
    const int gemm_blocks_h1  = (N_NODES - SPLIT) / GEMM_BM;// 312
    const int gb_h0 = (SPLIT + 7) / 8;                      // gather blocks h0
    const int gb_h1 = (N_NODES - SPLIT + 7) / 8;
    const int gb_all = (N_NODES + 7) / 8;

    __half* A16; cudaGetSymbolAddress((void**)&A16, g_A16);
    __half* B16; cudaGetSymbolAddress((void**)&B16, g_B16);
    __half* C16; cudaGetSymbolAddress((void**)&C16, g_C16);

    // fork: single-pass CSR build on side stream
    cudaEventRecord(ev_fork, 0);
    cudaStreamWaitEvent(s1, ev_fork, 0);
    init_kernel<<<(N_NODES + 255) / 256, 256, 0, s1>>>();
    fill_direct_kernel<<<(N_EDGES + 255) / 256, 256, 0, s1>>>(row, col);
    dis_kernel<<<(N_NODES + 255) / 256, 256, 0, s1>>>();
    cudaEventRecord(ev_join, s1);

    // layer 1: gemm over all rows (overlapped with CSR build)
    gemm_wmma_kernel<true><<<gemm_blocks_all, 256, GEMM_SMEM_BYTES>>>(x, W1, B16, 0);
    cudaStreamWaitEvent(0, ev_join, 0);

    // ---- layer boundary 1: gather1(B16->A16) pipelined with gemm2(A16->C16) --
    gather_kernel<0><<<gb_h0, 256>>>(B16, A16, b1, bat, 0, SPLIT);
    cudaEventRecord(evA, 0);
    gather_kernel<0><<<gb_h1, 256>>>(B16, A16, b1, bat, SPLIT, N_NODES);
    cudaStreamWaitEvent(s1, evA, 0);
    gemm_wmma_kernel<false><<<gemm_blocks_h0, 256, GEMM_SMEM_BYTES, s1>>>(A16, W2, C16, 0);
    cudaEventRecord(evB, s1);
    gemm_wmma_kernel<false><<<gemm_blocks_h1, 256, GEMM_SMEM_BYTES>>>(A16, W2, C16, SPLIT);
    cudaStreamWaitEvent(0, evB, 0);

    // ---- layer boundary 2: gather2(C16->A16) pipelined with gemm3(A16->B16) --
    gather_kernel<0><<<gb_h0, 256>>>(C16, A16, b2, bat, 0, SPLIT);
    cudaEventRecord(evC, 0);
    gather_kernel<0><<<gb_h1, 256>>>(C16, A16, b2, bat, SPLIT, N_NODES);
    cudaStreamWaitEvent(s1, evC, 0);
    gemm_wmma_kernel<false><<<gemm_blocks_h0, 256, GEMM_SMEM_BYTES, s1>>>(A16, W3, B16, 0);
    cudaEventRecord(evE, s1);
    gemm_wmma_kernel<false><<<gemm_blocks_h1, 256, GEMM_SMEM_BYTES>>>(A16, W3, B16, SPLIT);
    cudaStreamWaitEvent(0, evE, 0);

    // ---- layer 3 output: gather + pool over all nodes ----
    gather_kernel<1><<<gb_all, 256>>>(B16, A16, b3, bat, 0, N_NODES);

    final_kernel<<<N_GRAPHS, 32>>>(Wl, bl, out);
}